// round 1
// baseline (speedup 1.0000x reference)
#include <cuda_runtime.h>
#include <math.h>

// Problem constants
#define B_ 8
#define S_ 2048
#define D_ 1024
#define H_ 1024
#define M_ (B_*S_)   // 16384 rows

// Scratch (allocation-free rule: __device__ globals)
__device__ float g_a [(size_t)M_ * H_];   // a_t = 1 - z_t
__device__ float g_bv[(size_t)M_ * H_];   // b_t = z_t * g(pre_h)
__device__ float g_x1[(size_t)M_ * H_];   // layer-0 hidden output

// ---------------------------------------------------------------------------
// Fused dual-GEMM + gate epilogue.
// Computes k = X*Wz^T + bz and ph = X*Wh^T + bh for a 64x64 (m,h) tile,
// then writes a = sigmoid(-k), b = sigmoid(k) * g(ph).
// X:(M,D) row-major, Wz/Wh:(H,D) row-major (both K-contiguous).
// ---------------------------------------------------------------------------
#define BM 64
#define BN 64
#define BK 16

__global__ __launch_bounds__(256) void gemm_gates_kernel(
    const float* __restrict__ X,
    const float* __restrict__ Wz, const float* __restrict__ bz,
    const float* __restrict__ Wh, const float* __restrict__ bh,
    float* __restrict__ Aout, float* __restrict__ Bout)
{
    __shared__ float As[BK][BM + 4];
    __shared__ float Zs[BK][BN + 4];
    __shared__ float Hs[BK][BN + 4];

    const int tid = threadIdx.x;
    const int bm = blockIdx.y * BM;
    const int bn = blockIdx.x * BN;

    // 16x16 thread grid, each thread owns a 4x4 output microtile (for BOTH gemms)
    const int tx = tid & 15;   // n direction
    const int ty = tid >> 4;   // m direction

    // load mapping: one float4 per tile per k-step per thread
    const int lr = tid >> 2;           // row within 64
    const int lc = (tid & 3) << 2;     // col within 16

    const float* Xp = X  + (size_t)(bm + lr) * D_ + lc;
    const float* Zp = Wz + (size_t)(bn + lr) * D_ + lc;
    const float* Hp = Wh + (size_t)(bn + lr) * D_ + lc;

    float accZ[16], accH[16];
    #pragma unroll
    for (int i = 0; i < 16; i++) { accZ[i] = 0.f; accH[i] = 0.f; }

    for (int k0 = 0; k0 < D_; k0 += BK) {
        float4 xa = *(const float4*)(Xp + k0);
        float4 za = *(const float4*)(Zp + k0);
        float4 ha = *(const float4*)(Hp + k0);
        As[lc+0][lr] = xa.x; As[lc+1][lr] = xa.y; As[lc+2][lr] = xa.z; As[lc+3][lr] = xa.w;
        Zs[lc+0][lr] = za.x; Zs[lc+1][lr] = za.y; Zs[lc+2][lr] = za.z; Zs[lc+3][lr] = za.w;
        Hs[lc+0][lr] = ha.x; Hs[lc+1][lr] = ha.y; Hs[lc+2][lr] = ha.z; Hs[lc+3][lr] = ha.w;
        __syncthreads();

        #pragma unroll
        for (int kk = 0; kk < BK; kk++) {
            float4 av = *(const float4*)&As[kk][ty << 2];
            float4 zv = *(const float4*)&Zs[kk][tx << 2];
            float4 hv = *(const float4*)&Hs[kk][tx << 2];
            const float am[4] = {av.x, av.y, av.z, av.w};
            const float zn[4] = {zv.x, zv.y, zv.z, zv.w};
            const float hn[4] = {hv.x, hv.y, hv.z, hv.w};
            #pragma unroll
            for (int i = 0; i < 4; i++) {
                #pragma unroll
                for (int j = 0; j < 4; j++) {
                    accZ[i*4+j] = fmaf(am[i], zn[j], accZ[i*4+j]);
                    accH[i*4+j] = fmaf(am[i], hn[j], accH[i*4+j]);
                }
            }
        }
        __syncthreads();
    }

    // Epilogue: gate math, write a and b
    #pragma unroll
    for (int i = 0; i < 4; i++) {
        const int m = bm + (ty << 2) + i;
        #pragma unroll
        for (int j = 0; j < 4; j++) {
            const int h = bn + (tx << 2) + j;
            float kv = accZ[i*4+j] + bz[h];
            float ph = accH[i*4+j] + bh[h];
            // z = sigmoid(kv); a = sigmoid(-kv) computed directly (no 1-z cancellation)
            float z = 1.f / (1.f + expf(-kv));
            float a = 1.f / (1.f + expf( kv));
            float g = (ph >= 0.f) ? (ph + 0.5f) : (1.f / (1.f + expf(-ph)));
            size_t o = (size_t)m * H_ + h;
            Aout[o] = a;
            Bout[o] = z * g;
        }
    }
}

// ---------------------------------------------------------------------------
// Sequential scan: h_t = a_t * h_{t-1} + b_t, h_{-1} = 0.5.
// One thread per (batch, channel); coalesced across channels.
// ---------------------------------------------------------------------------
__global__ __launch_bounds__(128) void scan_kernel(
    const float* __restrict__ A, const float* __restrict__ Bv,
    float* __restrict__ out)
{
    const int b = blockIdx.y;
    const int h = blockIdx.x * 128 + threadIdx.x;
    size_t idx = ((size_t)b * S_) * H_ + h;
    float hv = 0.5f;
    for (int t = 0; t < S_; t += 4) {
        // batch the 8 independent loads so they overlap DRAM latency
        float a0 = A[idx];          float b0 = Bv[idx];
        float a1 = A[idx +   H_];   float b1 = Bv[idx +   H_];
        float a2 = A[idx + 2*H_];   float b2 = Bv[idx + 2*H_];
        float a3 = A[idx + 3*H_];   float b3 = Bv[idx + 3*H_];
        hv = fmaf(a0, hv, b0); out[idx]        = hv;
        hv = fmaf(a1, hv, b1); out[idx +   H_] = hv;
        hv = fmaf(a2, hv, b2); out[idx + 2*H_] = hv;
        hv = fmaf(a3, hv, b3); out[idx + 3*H_] = hv;
        idx += (size_t)4 * H_;
    }
}

// ---------------------------------------------------------------------------
// Launch: layer 0 (x -> g_x1), layer 1 (g_x1 -> d_out)
// ---------------------------------------------------------------------------
extern "C" void kernel_launch(void* const* d_in, const int* in_sizes, int n_in,
                              void* d_out, int out_size)
{
    const float* x  = (const float*)d_in[0];
    const float* Wz = (const float*)d_in[1];
    const float* bz = (const float*)d_in[2];
    const float* Wh = (const float*)d_in[3];
    const float* bh = (const float*)d_in[4];
    float* out = (float*)d_out;

    float *a_ptr, *b_ptr, *x1_ptr;
    cudaGetSymbolAddress((void**)&a_ptr,  g_a);
    cudaGetSymbolAddress((void**)&b_ptr,  g_bv);
    cudaGetSymbolAddress((void**)&x1_ptr, g_x1);

    dim3 gg(H_ / BN, M_ / BM);   // (16, 256)
    dim3 gs(H_ / 128, B_);       // (8, 8)

    // Layer 0
    gemm_gates_kernel<<<gg, 256>>>(x, Wz, bz, Wh, bh, a_ptr, b_ptr);
    scan_kernel<<<gs, 128>>>(a_ptr, b_ptr, x1_ptr);

    // Layer 1
    gemm_gates_kernel<<<gg, 256>>>(x1_ptr,
                                   Wz + (size_t)H_ * D_, bz + H_,
                                   Wh + (size_t)H_ * D_, bh + H_,
                                   a_ptr, b_ptr);
    scan_kernel<<<gs, 128>>>(a_ptr, b_ptr, out);
}

// round 3
// speedup vs baseline: 2.8138x; 2.8138x over previous
#include <cuda_runtime.h>
#include <cstdint>
#include <math.h>

// ---------------- problem constants ----------------
#define B_  8
#define S_  2048
#define D_  1024
#define H_  1024
#define M_  (B_*S_)        // 16384
#define N2_ 2048           // interleaved (k,ph) output width
#define NC_ 16             // scan chunks
#define CL_ 128            // chunk length

// ---------------- scratch ----------------
__device__ float g_Xr  [(size_t)M_ * D_];     // tf32-rounded GEMM input
__device__ float g_Wc  [(size_t)N2_ * D_];    // interleaved, tf32-rounded weights
__device__ float g_gA  [(size_t)M_ * H_];     // a_t
__device__ float g_gB  [(size_t)M_ * H_];     // b_t
__device__ float g_As  [(size_t)B_ * NC_ * H_];
__device__ float g_Bs  [(size_t)B_ * NC_ * H_];
__device__ float g_Hs  [(size_t)B_ * NC_ * H_];

// ---------------- helpers ----------------
__device__ __forceinline__ uint32_t smem_u32(const void* p) {
    uint32_t a;
    asm("{ .reg .u64 t; cvta.to.shared.u64 t, %1; cvt.u32.u64 %0, t; }" : "=r"(a) : "l"(p));
    return a;
}
__device__ __forceinline__ float rna_tf32(float v) {
    uint32_t r;
    asm("cvt.rna.tf32.f32 %0, %1;" : "=r"(r) : "f"(v));
    return __uint_as_float(r);
}
__device__ __forceinline__ void cpasync16(uint32_t dst, const void* src) {
    asm volatile("cp.async.cg.shared.global [%0], [%1], 16;" :: "r"(dst), "l"(src));
}
#define CP_COMMIT() asm volatile("cp.async.commit_group;" ::: "memory")

__device__ __forceinline__ void mma_tf32(float* c,
    uint32_t a0, uint32_t a1, uint32_t a2, uint32_t a3, uint32_t b0, uint32_t b1)
{
    asm volatile(
        "mma.sync.aligned.m16n8k8.row.col.f32.tf32.tf32.f32 "
        "{%0,%1,%2,%3}, {%4,%5,%6,%7}, {%8,%9}, {%0,%1,%2,%3};"
        : "+f"(c[0]), "+f"(c[1]), "+f"(c[2]), "+f"(c[3])
        : "r"(a0), "r"(a1), "r"(a2), "r"(a3), "r"(b0), "r"(b1));
}

__device__ __forceinline__ void gates2(float kv, float ph, float& a, float& b) {
    float z = __frcp_rn(1.f + __expf(-kv));   // sigmoid(kv)
    a = __frcp_rn(1.f + __expf(kv));          // sigmoid(-kv), overflow-safe
    float g = (ph >= 0.f) ? (ph + 0.5f) : __frcp_rn(1.f + __expf(-ph));
    b = z * g;
}

// ---------------- tf32 rounding copy ----------------
__global__ __launch_bounds__(256) void round_kernel(
    const float4* __restrict__ src, float4* __restrict__ dst, int n4)
{
    int stride = gridDim.x * blockDim.x;
    for (int i = blockIdx.x * blockDim.x + threadIdx.x; i < n4; i += stride) {
        float4 v = src[i];
        v.x = rna_tf32(v.x); v.y = rna_tf32(v.y);
        v.z = rna_tf32(v.z); v.w = rna_tf32(v.w);
        dst[i] = v;
    }
}

// interleave: Wc[2h][:] = rna(Wz[h][:]), Wc[2h+1][:] = rna(Wh[h][:])
__global__ __launch_bounds__(256) void interleave_kernel(
    const float4* __restrict__ Wz, const float4* __restrict__ Wh, float4* __restrict__ Wc)
{
    int i = blockIdx.x * 256 + threadIdx.x;      // over H_*D_/4 = 262144
    int h = i >> 8;                               // D_/4 = 256 segs/row
    int s = i & 255;
    float4 vz = Wz[i], vh = Wh[i];
    vz.x = rna_tf32(vz.x); vz.y = rna_tf32(vz.y); vz.z = rna_tf32(vz.z); vz.w = rna_tf32(vz.w);
    vh.x = rna_tf32(vh.x); vh.y = rna_tf32(vh.y); vh.z = rna_tf32(vh.z); vh.w = rna_tf32(vh.w);
    Wc[(size_t)(2*h)   * 256 + s] = vz;
    Wc[(size_t)(2*h+1) * 256 + s] = vh;
}

// ============================================================================
// tf32 mma.sync GEMM, tile 128x128, BK=32, 3-stage cp.async, fused gate epilogue
// ============================================================================
#define BM 128
#define BN 128
#define BK 32
#define ASTRIDE 36                       // floats per smem row (pad 4)
#define STG_FLOATS (2 * BM * ASTRIDE)    // A + B per stage = 9216 floats
#define STG_BYTES  (STG_FLOATS * 4)      // 36864
#define GEMM_SMEM  (3 * STG_BYTES)       // 110592

__device__ __forceinline__ void load_stage(
    uint32_t sb, const float* __restrict__ Ag, const float* __restrict__ Bg,
    int k0, int tid)
{
    #pragma unroll
    for (int i = 0; i < 4; i++) {
        int s = tid + i * 256;
        int r = s >> 3, c = (s & 7) << 2;
        cpasync16(sb + (uint32_t)(r * ASTRIDE + c) * 4, Ag + (size_t)r * D_ + k0 + c);
    }
    #pragma unroll
    for (int i = 0; i < 4; i++) {
        int s = tid + i * 256;
        int r = s >> 3, c = (s & 7) << 2;
        cpasync16(sb + (uint32_t)(BM * ASTRIDE + r * ASTRIDE + c) * 4,
                  Bg + (size_t)r * D_ + k0 + c);
    }
    CP_COMMIT();
}

__global__ __launch_bounds__(256, 1) void gemm_tf32_kernel(
    const float* __restrict__ X, const float* __restrict__ Wc,
    const float* __restrict__ bz, const float* __restrict__ bh,
    float* __restrict__ gA, float* __restrict__ gB)
{
    extern __shared__ __align__(16) float sm[];
    const uint32_t sb = smem_u32(sm);
    const int tid = threadIdx.x;
    const int lane = tid & 31, wid = tid >> 5;
    const int g = lane >> 2, tg = lane & 3;
    const int wm = (wid >> 2) * 64;      // warp m-offset (0/64)
    const int wn = (wid & 3) * 32;       // warp n-offset (0/32/64/96)
    const int bm = blockIdx.y * BM;
    const int bn = blockIdx.x * BN;

    const float* Ag = X  + (size_t)bm * D_;
    const float* Bg = Wc + (size_t)bn * D_;

    float c[4][4][4];
    #pragma unroll
    for (int mt = 0; mt < 4; mt++)
        #pragma unroll
        for (int nt = 0; nt < 4; nt++)
            #pragma unroll
            for (int r = 0; r < 4; r++) c[mt][nt][r] = 0.f;

    // prologue: stages 0,1
    load_stage(sb,             Ag, Bg, 0,  tid);
    load_stage(sb + STG_BYTES, Ag, Bg, BK, tid);

    const int NK = D_ / BK;   // 32
    for (int kt = 0; kt < NK; kt++) {
        asm volatile("cp.async.wait_group 1;" ::: "memory");
        __syncthreads();
        if (kt + 2 < NK)
            load_stage(sb + (uint32_t)((kt + 2) % 3) * STG_BYTES, Ag, Bg, (kt + 2) * BK, tid);
        else
            CP_COMMIT();

        const float* As = sm + (kt % 3) * STG_FLOATS;
        const float* Bs = As + BM * ASTRIDE;

        #pragma unroll
        for (int ks = 0; ks < 4; ks++) {
            const int kb = ks * 8;
            uint32_t a[4][4], b[4][2];
            #pragma unroll
            for (int mt = 0; mt < 4; mt++) {
                const int m = wm + mt * 16 + g;
                a[mt][0] = __float_as_uint(As[(m)     * ASTRIDE + kb + tg]);
                a[mt][1] = __float_as_uint(As[(m + 8) * ASTRIDE + kb + tg]);
                a[mt][2] = __float_as_uint(As[(m)     * ASTRIDE + kb + 4 + tg]);
                a[mt][3] = __float_as_uint(As[(m + 8) * ASTRIDE + kb + 4 + tg]);
            }
            #pragma unroll
            for (int nt = 0; nt < 4; nt++) {
                const int n = wn + nt * 8 + g;
                b[nt][0] = __float_as_uint(Bs[n * ASTRIDE + kb + tg]);
                b[nt][1] = __float_as_uint(Bs[n * ASTRIDE + kb + 4 + tg]);
            }
            #pragma unroll
            for (int mt = 0; mt < 4; mt++)
                #pragma unroll
                for (int nt = 0; nt < 4; nt++)
                    mma_tf32(c[mt][nt], a[mt][0], a[mt][1], a[mt][2], a[mt][3],
                             b[nt][0], b[nt][1]);
        }
    }

    // epilogue: columns are interleaved (k, ph) pairs -> gates -> gA/gB
    const int hbase = (bn >> 1) + (wn >> 1);   // 64 h per block
    #pragma unroll
    for (int nt = 0; nt < 4; nt++) {
        const int h = hbase + nt * 4 + tg;
        const float bzv = bz[h], bhv = bh[h];
        #pragma unroll
        for (int mt = 0; mt < 4; mt++) {
            const int m = bm + wm + mt * 16 + g;
            float a0, b0, a1, b1;
            gates2(c[mt][nt][0] + bzv, c[mt][nt][1] + bhv, a0, b0);
            gates2(c[mt][nt][2] + bzv, c[mt][nt][3] + bhv, a1, b1);
            gA[(size_t)m * H_ + h]       = a0;
            gB[(size_t)m * H_ + h]       = b0;
            gA[(size_t)(m + 8) * H_ + h] = a1;
            gB[(size_t)(m + 8) * H_ + h] = b1;
        }
    }
}

// ============================================================================
// chunked scan (pure streaming fmaf; gates precomputed)
// ============================================================================
__global__ __launch_bounds__(128) void scanA_kernel(
    const float* __restrict__ gA, const float* __restrict__ gB,
    float* __restrict__ As, float* __restrict__ Bs)
{
    const int h = blockIdx.x * 128 + threadIdx.x;
    const int c = blockIdx.y, b = blockIdx.z;
    const size_t m0 = (size_t)b * S_ + (size_t)c * CL_;
    const float* pa = gA + m0 * H_ + h;
    const float* pb = gB + m0 * H_ + h;
    float A = 1.f, Bv = 0.f;
    for (int t = 0; t < CL_; t += 4) {
        float a0 = pa[0],     b0 = pb[0];
        float a1 = pa[H_],    b1 = pb[H_];
        float a2 = pa[2*H_],  b2 = pb[2*H_];
        float a3 = pa[3*H_],  b3 = pb[3*H_];
        pa += 4 * H_; pb += 4 * H_;
        Bv = fmaf(a0, Bv, b0); A *= a0;
        Bv = fmaf(a1, Bv, b1); A *= a1;
        Bv = fmaf(a2, Bv, b2); A *= a2;
        Bv = fmaf(a3, Bv, b3); A *= a3;
    }
    const size_t o = ((size_t)b * NC_ + c) * H_ + h;
    As[o] = A; Bs[o] = Bv;
}

__global__ __launch_bounds__(128) void scanB_kernel(
    const float* __restrict__ As, const float* __restrict__ Bs, float* __restrict__ Hs)
{
    const int h = blockIdx.x * 128 + threadIdx.x;
    const int b = blockIdx.y;
    float hv = 0.5f;
    for (int c = 0; c < NC_; c++) {
        const size_t o = ((size_t)b * NC_ + c) * H_ + h;
        Hs[o] = hv;
        hv = fmaf(As[o], hv, Bs[o]);
    }
}

template<int MODE>   // 0: write tf32-rounded (next-layer GEMM input); 1: write fp32 out
__global__ __launch_bounds__(128) void scanC_kernel(
    const float* __restrict__ gA, const float* __restrict__ gB,
    const float* __restrict__ Hs, float* __restrict__ out)
{
    const int h = blockIdx.x * 128 + threadIdx.x;
    const int c = blockIdx.y, b = blockIdx.z;
    const size_t m0 = (size_t)b * S_ + (size_t)c * CL_;
    const float* pa = gA + m0 * H_ + h;
    const float* pb = gB + m0 * H_ + h;
    float hv = Hs[((size_t)b * NC_ + c) * H_ + h];
    float* po = out + m0 * H_ + h;
    for (int t = 0; t < CL_; t += 4) {
        float a0 = pa[0],     b0 = pb[0];
        float a1 = pa[H_],    b1 = pb[H_];
        float a2 = pa[2*H_],  b2 = pb[2*H_];
        float a3 = pa[3*H_],  b3 = pb[3*H_];
        pa += 4 * H_; pb += 4 * H_;
        hv = fmaf(a0, hv, b0); po[0]    = (MODE == 0) ? rna_tf32(hv) : hv;
        hv = fmaf(a1, hv, b1); po[H_]   = (MODE == 0) ? rna_tf32(hv) : hv;
        hv = fmaf(a2, hv, b2); po[2*H_] = (MODE == 0) ? rna_tf32(hv) : hv;
        hv = fmaf(a3, hv, b3); po[3*H_] = (MODE == 0) ? rna_tf32(hv) : hv;
        po += 4 * H_;
    }
}

// ============================================================================
// launch
// ============================================================================
extern "C" void kernel_launch(void* const* d_in, const int* in_sizes, int n_in,
                              void* d_out, int out_size)
{
    const float* x  = (const float*)d_in[0];
    const float* Wz = (const float*)d_in[1];
    const float* bz = (const float*)d_in[2];
    const float* Wh = (const float*)d_in[3];
    const float* bh = (const float*)d_in[4];
    float* out = (float*)d_out;

    float *Xr, *Wc, *gA, *gB, *As, *Bs, *Hs;
    cudaGetSymbolAddress((void**)&Xr, g_Xr);
    cudaGetSymbolAddress((void**)&Wc, g_Wc);
    cudaGetSymbolAddress((void**)&gA, g_gA);
    cudaGetSymbolAddress((void**)&gB, g_gB);
    cudaGetSymbolAddress((void**)&As, g_As);
    cudaGetSymbolAddress((void**)&Bs, g_Bs);
    cudaGetSymbolAddress((void**)&Hs, g_Hs);

    cudaFuncSetAttribute(gemm_tf32_kernel,
                         cudaFuncAttributeMaxDynamicSharedMemorySize, GEMM_SMEM);

    const size_t HD = (size_t)H_ * D_;
    dim3 gemm_grid(N2_ / BN, M_ / BM);     // (16, 128)
    dim3 scanAC_grid(H_ / 128, NC_, B_);   // (8, 16, 8)
    dim3 scanB_grid(H_ / 128, B_);         // (8, 8)

    round_kernel<<<512, 256>>>((const float4*)x, (float4*)Xr, (int)((size_t)M_ * D_ / 4));

    for (int l = 0; l < 2; l++) {
        interleave_kernel<<<1024, 256>>>((const float4*)(Wz + l * HD),
                                         (const float4*)(Wh + l * HD), (float4*)Wc);
        gemm_tf32_kernel<<<gemm_grid, 256, GEMM_SMEM>>>(Xr, Wc,
                                                        bz + l * H_, bh + l * H_, gA, gB);
        scanA_kernel<<<scanAC_grid, 128>>>(gA, gB, As, Bs);
        scanB_kernel<<<scanB_grid, 128>>>(As, Bs, Hs);
        if (l == 0)
            scanC_kernel<0><<<scanAC_grid, 128>>>(gA, gB, Hs, Xr);
        else
            scanC_kernel<1><<<scanAC_grid, 128>>>(gA, gB, Hs, out);
    }
}

// round 4
// speedup vs baseline: 3.3670x; 1.1966x over previous
#include <cuda_runtime.h>
#include <cstdint>
#include <math.h>

// ---------------- problem constants ----------------
#define B_  8
#define S_  2048
#define D_  1024
#define H_  1024
#define M_  (B_*S_)        // 16384
#define N2_ 2048           // interleaved (k,ph) output width
#define NC_ 16             // scan chunks
#define CL_ 128            // chunk length

// ---------------- scratch ----------------
__device__ float g_Xr  [(size_t)M_ * D_];     // tf32-rounded, K-permuted GEMM input
__device__ float g_Wc  [(size_t)N2_ * D_];    // interleaved rows, K-permuted, tf32-rounded
__device__ float g_gA  [(size_t)M_ * H_];     // a_t
__device__ float g_gB  [(size_t)M_ * H_];     // b_t
__device__ float g_As  [(size_t)B_ * NC_ * H_];
__device__ float g_Bs  [(size_t)B_ * NC_ * H_];
__device__ float g_Hs  [(size_t)B_ * NC_ * H_];

// ---------------- helpers ----------------
__device__ __forceinline__ uint32_t smem_u32(const void* p) {
    uint32_t a;
    asm("{ .reg .u64 t; cvta.to.shared.u64 t, %1; cvt.u32.u64 %0, t; }" : "=r"(a) : "l"(p));
    return a;
}
__device__ __forceinline__ float rna_tf32(float v) {
    uint32_t r;
    asm("cvt.rna.tf32.f32 %0, %1;" : "=r"(r) : "f"(v));
    return __uint_as_float(r);
}
__device__ __forceinline__ void cpasync16(uint32_t dst, const void* src) {
    asm volatile("cp.async.cg.shared.global [%0], [%1], 16;" :: "r"(dst), "l"(src));
}
#define CP_COMMIT() asm volatile("cp.async.commit_group;" ::: "memory")

__device__ __forceinline__ void mma_tf32(float* c,
    uint32_t a0, uint32_t a1, uint32_t a2, uint32_t a3, uint32_t b0, uint32_t b1)
{
    asm volatile(
        "mma.sync.aligned.m16n8k8.row.col.f32.tf32.tf32.f32 "
        "{%0,%1,%2,%3}, {%4,%5,%6,%7}, {%8,%9}, {%0,%1,%2,%3};"
        : "+f"(c[0]), "+f"(c[1]), "+f"(c[2]), "+f"(c[3])
        : "r"(a0), "r"(a1), "r"(a2), "r"(a3), "r"(b0), "r"(b1));
}

__device__ __forceinline__ void gates2(float kv, float ph, float& a, float& b) {
    float z = __frcp_rn(1.f + __expf(-kv));   // sigmoid(kv)
    a = __frcp_rn(1.f + __expf(kv));          // sigmoid(-kv), overflow-safe
    float g = (ph >= 0.f) ? (ph + 0.5f) : __frcp_rn(1.f + __expf(-ph));
    b = z * g;
}

// K-permutation within each 8-group: src order (0..7) -> dst (0,4,1,5,2,6,3,7)
// so that (k, k+4) pairs are adjacent (columns 2k, 2k+1).
__device__ __forceinline__ void perm8(const float4 v0, const float4 v1,
                                      float4& o0, float4& o1)
{
    o0 = make_float4(rna_tf32(v0.x), rna_tf32(v1.x), rna_tf32(v0.y), rna_tf32(v1.y));
    o1 = make_float4(rna_tf32(v0.z), rna_tf32(v1.z), rna_tf32(v0.w), rna_tf32(v1.w));
}

// ---------------- tf32 round + K-permute copy ----------------
__global__ __launch_bounds__(256) void round_kernel(
    const float4* __restrict__ src, float4* __restrict__ dst, int n8)
{
    int stride = gridDim.x * blockDim.x;
    for (int i = blockIdx.x * blockDim.x + threadIdx.x; i < n8; i += stride) {
        float4 o0, o1;
        perm8(src[2*i], src[2*i+1], o0, o1);
        dst[2*i] = o0; dst[2*i+1] = o1;
    }
}

// interleave rows: Wc[2h] = perm(rna(Wz[h])), Wc[2h+1] = perm(rna(Wh[h]))
__global__ __launch_bounds__(256) void interleave_kernel(
    const float4* __restrict__ Wz, const float4* __restrict__ Wh, float4* __restrict__ Wc)
{
    int i = blockIdx.x * 256 + threadIdx.x;      // over H_*D_/8 = 131072 segments
    int h = i >> 7;                              // D_/8 = 128 segs per row
    int s = i & 127;
    float4 z0, z1, h0, h1;
    perm8(Wz[2*i], Wz[2*i+1], z0, z1);
    perm8(Wh[2*i], Wh[2*i+1], h0, h1);
    float4* rz = Wc + (size_t)(2*h)   * 256 + 2*s;
    float4* rh = Wc + (size_t)(2*h+1) * 256 + 2*s;
    rz[0] = z0; rz[1] = z1;
    rh[0] = h0; rh[1] = h1;
}

// ============================================================================
// tf32 mma.sync GEMM, tile 128x256, warptile 64x64, BK=32, 3-stage cp.async,
// LDS.64 fragment loads (K-permuted layout), fused gate epilogue
// ============================================================================
#define BM 128
#define BN 256
#define BK 32
#define AS 40                            // floats per smem row: (AS/2) % 16 == 4
#define B_OFF (BM * AS)                  // B rows start (floats)
#define STG_FLOATS ((BM + BN) * AS)      // 15360
#define STG_BYTES  (STG_FLOATS * 4)      // 61440
#define GEMM_SMEM  (3 * STG_BYTES)       // 184320

__device__ __forceinline__ void load_stage(
    uint32_t sb, const float* __restrict__ Ag, const float* __restrict__ Bg,
    int k0, int tid)
{
    #pragma unroll
    for (int i = 0; i < 4; i++) {        // A: 128 rows x 8 chunks
        int s = tid + i * 256;
        int r = s >> 3, c = (s & 7) << 2;
        cpasync16(sb + (uint32_t)(r * AS + c) * 4, Ag + (size_t)r * D_ + k0 + c);
    }
    #pragma unroll
    for (int i = 0; i < 8; i++) {        // B: 256 rows x 8 chunks
        int s = tid + i * 256;
        int r = s >> 3, c = (s & 7) << 2;
        cpasync16(sb + (uint32_t)(B_OFF + r * AS + c) * 4, Bg + (size_t)r * D_ + k0 + c);
    }
    CP_COMMIT();
}

__global__ __launch_bounds__(256, 1) void gemm_tf32_kernel(
    const float* __restrict__ X, const float* __restrict__ Wc,
    const float* __restrict__ bz, const float* __restrict__ bh,
    float* __restrict__ gA, float* __restrict__ gB)
{
    extern __shared__ __align__(16) float sm[];
    const uint32_t sb = smem_u32(sm);
    const int tid = threadIdx.x;
    const int lane = tid & 31, wid = tid >> 5;
    const int g = lane >> 2, tg = lane & 3;
    const int wm = (wid >> 2) * 64;      // 0 / 64
    const int wn = (wid & 3) * 64;       // 0 / 64 / 128 / 192
    const int bm = blockIdx.y * BM;
    const int bn = blockIdx.x * BN;

    const float* Ag = X  + (size_t)bm * D_;
    const float* Bg = Wc + (size_t)bn * D_;

    float c[4][8][4];
    #pragma unroll
    for (int mt = 0; mt < 4; mt++)
        #pragma unroll
        for (int nt = 0; nt < 8; nt++)
            #pragma unroll
            for (int r = 0; r < 4; r++) c[mt][nt][r] = 0.f;

    load_stage(sb,             Ag, Bg, 0,  tid);
    load_stage(sb + STG_BYTES, Ag, Bg, BK, tid);

    const int NK = D_ / BK;   // 32
    for (int kt = 0; kt < NK; kt++) {
        asm volatile("cp.async.wait_group 1;" ::: "memory");
        __syncthreads();
        if (kt + 2 < NK)
            load_stage(sb + (uint32_t)((kt + 2) % 3) * STG_BYTES, Ag, Bg, (kt + 2) * BK, tid);
        else
            CP_COMMIT();

        const float* As = sm + (kt % 3) * STG_FLOATS;
        const float* Bs = As + B_OFF;

        #pragma unroll
        for (int ks = 0; ks < 4; ks++) {
            const int kb = ks * 8 + 2 * tg;   // permuted pair (k=tg, k=tg+4)
            float2 alo[4], ahi[4], bf[8];
            #pragma unroll
            for (int mt = 0; mt < 4; mt++) {
                const int m = wm + mt * 16 + g;
                alo[mt] = *(const float2*)&As[m * AS + kb];
                ahi[mt] = *(const float2*)&As[(m + 8) * AS + kb];
            }
            #pragma unroll
            for (int nt = 0; nt < 8; nt++) {
                const int n = wn + nt * 8 + g;
                bf[nt] = *(const float2*)&Bs[n * AS + kb];
            }
            #pragma unroll
            for (int mt = 0; mt < 4; mt++)
                #pragma unroll
                for (int nt = 0; nt < 8; nt++)
                    mma_tf32(c[mt][nt],
                             __float_as_uint(alo[mt].x), __float_as_uint(ahi[mt].x),
                             __float_as_uint(alo[mt].y), __float_as_uint(ahi[mt].y),
                             __float_as_uint(bf[nt].x),  __float_as_uint(bf[nt].y));
        }
    }

    // epilogue: C columns are interleaved (k, ph) pairs -> gates -> gA/gB
    const int hbase = (bn >> 1) + (wn >> 1);   // 128 h per block, 32 per warp
    #pragma unroll
    for (int nt = 0; nt < 8; nt++) {
        const int h = hbase + nt * 4 + tg;
        const float bzv = bz[h], bhv = bh[h];
        #pragma unroll
        for (int mt = 0; mt < 4; mt++) {
            const int m = bm + wm + mt * 16 + g;
            float a0, b0, a1, b1;
            gates2(c[mt][nt][0] + bzv, c[mt][nt][1] + bhv, a0, b0);
            gates2(c[mt][nt][2] + bzv, c[mt][nt][3] + bhv, a1, b1);
            gA[(size_t)m * H_ + h]       = a0;
            gB[(size_t)m * H_ + h]       = b0;
            gA[(size_t)(m + 8) * H_ + h] = a1;
            gB[(size_t)(m + 8) * H_ + h] = b1;
        }
    }
}

// ============================================================================
// chunked scan (gates precomputed in GEMM epilogue)
// ============================================================================
__global__ __launch_bounds__(128) void scanA_kernel(
    const float* __restrict__ gA, const float* __restrict__ gB,
    float* __restrict__ As, float* __restrict__ Bs)
{
    const int h = blockIdx.x * 128 + threadIdx.x;
    const int c = blockIdx.y, b = blockIdx.z;
    const size_t m0 = (size_t)b * S_ + (size_t)c * CL_;
    const float* pa = gA + m0 * H_ + h;
    const float* pb = gB + m0 * H_ + h;
    float A = 1.f, Bv = 0.f;
    for (int t = 0; t < CL_; t += 4) {
        float a0 = pa[0],     b0 = pb[0];
        float a1 = pa[H_],    b1 = pb[H_];
        float a2 = pa[2*H_],  b2 = pb[2*H_];
        float a3 = pa[3*H_],  b3 = pb[3*H_];
        pa += 4 * H_; pb += 4 * H_;
        Bv = fmaf(a0, Bv, b0); A *= a0;
        Bv = fmaf(a1, Bv, b1); A *= a1;
        Bv = fmaf(a2, Bv, b2); A *= a2;
        Bv = fmaf(a3, Bv, b3); A *= a3;
    }
    const size_t o = ((size_t)b * NC_ + c) * H_ + h;
    As[o] = A; Bs[o] = Bv;
}

__global__ __launch_bounds__(128) void scanB_kernel(
    const float* __restrict__ As, const float* __restrict__ Bs, float* __restrict__ Hs)
{
    const int h = blockIdx.x * 128 + threadIdx.x;
    const int b = blockIdx.y;
    float hv = 0.5f;
    for (int c = 0; c < NC_; c++) {
        const size_t o = ((size_t)b * NC_ + c) * H_ + h;
        Hs[o] = hv;
        hv = fmaf(As[o], hv, Bs[o]);
    }
}

template<int MODE>   // 0: write tf32-rounded + K-permuted (next-layer GEMM input); 1: fp32 out
__global__ __launch_bounds__(128) void scanC_kernel(
    const float* __restrict__ gA, const float* __restrict__ gB,
    const float* __restrict__ Hs, float* __restrict__ out)
{
    const int h = blockIdx.x * 128 + threadIdx.x;
    const int c = blockIdx.y, b = blockIdx.z;
    const size_t m0 = (size_t)b * S_ + (size_t)c * CL_;
    const float* pa = gA + m0 * H_ + h;
    const float* pb = gB + m0 * H_ + h;
    float hv = Hs[((size_t)b * NC_ + c) * H_ + h];
    // output column: permuted for GEMM input, identity for final output
    const int hp = (MODE == 0) ? ((h & ~7) | (((h & 3) << 1) | ((h & 7) >> 2))) : h;
    float* po = out + m0 * H_ + hp;
    for (int t = 0; t < CL_; t += 4) {
        float a0 = pa[0],     b0 = pb[0];
        float a1 = pa[H_],    b1 = pb[H_];
        float a2 = pa[2*H_],  b2 = pb[2*H_];
        float a3 = pa[3*H_],  b3 = pb[3*H_];
        pa += 4 * H_; pb += 4 * H_;
        hv = fmaf(a0, hv, b0); po[0]    = (MODE == 0) ? rna_tf32(hv) : hv;
        hv = fmaf(a1, hv, b1); po[H_]   = (MODE == 0) ? rna_tf32(hv) : hv;
        hv = fmaf(a2, hv, b2); po[2*H_] = (MODE == 0) ? rna_tf32(hv) : hv;
        hv = fmaf(a3, hv, b3); po[3*H_] = (MODE == 0) ? rna_tf32(hv) : hv;
        po += 4 * H_;
    }
}

// ============================================================================
// launch
// ============================================================================
extern "C" void kernel_launch(void* const* d_in, const int* in_sizes, int n_in,
                              void* d_out, int out_size)
{
    const float* x  = (const float*)d_in[0];
    const float* Wz = (const float*)d_in[1];
    const float* bz = (const float*)d_in[2];
    const float* Wh = (const float*)d_in[3];
    const float* bh = (const float*)d_in[4];
    float* out = (float*)d_out;

    float *Xr, *Wc, *gA, *gB, *As, *Bs, *Hs;
    cudaGetSymbolAddress((void**)&Xr, g_Xr);
    cudaGetSymbolAddress((void**)&Wc, g_Wc);
    cudaGetSymbolAddress((void**)&gA, g_gA);
    cudaGetSymbolAddress((void**)&gB, g_gB);
    cudaGetSymbolAddress((void**)&As, g_As);
    cudaGetSymbolAddress((void**)&Bs, g_Bs);
    cudaGetSymbolAddress((void**)&Hs, g_Hs);

    cudaFuncSetAttribute(gemm_tf32_kernel,
                         cudaFuncAttributeMaxDynamicSharedMemorySize, GEMM_SMEM);

    const size_t HD = (size_t)H_ * D_;
    dim3 gemm_grid(N2_ / BN, M_ / BM);     // (8, 128)
    dim3 scanAC_grid(H_ / 128, NC_, B_);   // (8, 16, 8)
    dim3 scanB_grid(H_ / 128, B_);         // (8, 8)

    round_kernel<<<512, 256>>>((const float4*)x, (float4*)Xr, (int)((size_t)M_ * D_ / 8));

    for (int l = 0; l < 2; l++) {
        interleave_kernel<<<512, 256>>>((const float4*)(Wz + l * HD),
                                        (const float4*)(Wh + l * HD), (float4*)Wc);
        gemm_tf32_kernel<<<gemm_grid, 256, GEMM_SMEM>>>(Xr, Wc,
                                                        bz + l * H_, bh + l * H_, gA, gB);
        scanA_kernel<<<scanAC_grid, 128>>>(gA, gB, As, Bs);
        scanB_kernel<<<scanB_grid, 128>>>(As, Bs, Hs);
        if (l == 0)
            scanC_kernel<0><<<scanAC_grid, 128>>>(gA, gB, Hs, Xr);
        else
            scanC_kernel<1><<<scanAC_grid, 128>>>(gA, gB, Hs, out);
    }
}

// round 6
// speedup vs baseline: 5.0907x; 1.5119x over previous
#include <cuda_runtime.h>
#include <cuda_fp16.h>
#include <cstdint>
#include <math.h>

// ---------------- problem constants ----------------
#define B_  8
#define S_  2048
#define D_  1024
#define H_  1024
#define M_  (B_*S_)        // 16384
#define N2_ 2048           // interleaved (k,ph) output width
#define NC_ 16             // scan chunks
#define CL_ 128            // chunk length

// ---------------- scratch ----------------
__device__ __half g_Xh [(size_t)M_ * D_];     // fp16, K-permuted GEMM input
__device__ __half g_Wc [(size_t)N2_ * D_];    // fp16, interleaved rows, K-permuted
__device__ float  g_gA [(size_t)M_ * H_];     // a_t
__device__ float  g_gB [(size_t)M_ * H_];     // b_t
__device__ float  g_As [(size_t)B_ * NC_ * H_];
__device__ float  g_Bs [(size_t)B_ * NC_ * H_];
__device__ float  g_Hs [(size_t)B_ * NC_ * H_];

// ---------------- helpers ----------------
__device__ __forceinline__ uint32_t h2_as_u32(__half2 h) {
    union { __half2 h; uint32_t u; } cvt;
    cvt.h = h;
    return cvt.u;
}
__device__ __forceinline__ uint32_t smem_u32(const void* p) {
    uint32_t a;
    asm("{ .reg .u64 t; cvta.to.shared.u64 t, %1; cvt.u32.u64 %0, t; }" : "=r"(a) : "l"(p));
    return a;
}
__device__ __forceinline__ void cpasync16(uint32_t dst, const void* src) {
    asm volatile("cp.async.cg.shared.global [%0], [%1], 16;" :: "r"(dst), "l"(src));
}
#define CP_COMMIT() asm volatile("cp.async.commit_group;" ::: "memory")

__device__ __forceinline__ void mma_fp16(float* c,
    uint32_t a0, uint32_t a1, uint32_t a2, uint32_t a3, uint32_t b0, uint32_t b1)
{
    asm volatile(
        "mma.sync.aligned.m16n8k16.row.col.f32.f16.f16.f32 "
        "{%0,%1,%2,%3}, {%4,%5,%6,%7}, {%8,%9}, {%0,%1,%2,%3};"
        : "+f"(c[0]), "+f"(c[1]), "+f"(c[2]), "+f"(c[3])
        : "r"(a0), "r"(a1), "r"(a2), "r"(a3), "r"(b0), "r"(b1));
}

__device__ __forceinline__ void gates2(float kv, float ph, float& a, float& b) {
    float z = __frcp_rn(1.f + __expf(-kv));   // sigmoid(kv)
    a = __frcp_rn(1.f + __expf(kv));          // sigmoid(-kv), overflow-safe
    float g = (ph >= 0.f) ? (ph + 0.5f) : __frcp_rn(1.f + __expf(-ph));
    b = z * g;
}

// K-permutation within each 16-group: pair slots (0,1),(8,9),(2,3),(10,11),
// (4,5),(12,13),(6,7),(14,15) — so fragments {k=2t,2t+1, k=2t+8,2t+9} are 4
// contiguous halves (one LDS.64).
__device__ __forceinline__ void perm16(const float4 s0, const float4 s1,
                                       const float4 s2, const float4 s3,
                                       uint4& o0, uint4& o1)
{
    // s0,s1 = k0..7 ; s2,s3 = k8..15
    o0 = make_uint4(h2_as_u32(__floats2half2_rn(s0.x, s0.y)),   // pair0 (k0,k1)
                    h2_as_u32(__floats2half2_rn(s2.x, s2.y)),   // pair4 (k8,k9)
                    h2_as_u32(__floats2half2_rn(s0.z, s0.w)),   // pair1
                    h2_as_u32(__floats2half2_rn(s2.z, s2.w)));  // pair5
    o1 = make_uint4(h2_as_u32(__floats2half2_rn(s1.x, s1.y)),   // pair2
                    h2_as_u32(__floats2half2_rn(s3.x, s3.y)),   // pair6
                    h2_as_u32(__floats2half2_rn(s1.z, s1.w)),   // pair3
                    h2_as_u32(__floats2half2_rn(s3.z, s3.w)));  // pair7
}

// permuted column index for a single h within its 16-group
__device__ __forceinline__ int permcol16(int h) {
    int j = h & 15, q = j >> 1, r = j & 1;
    int slot = (q < 4) ? (2 * q) : (2 * (q - 4) + 1);
    return (h & ~15) | (slot * 2 + r);
}

// ---------------- fp32 -> fp16 + K-permute ----------------
__global__ __launch_bounds__(256) void round_kernel(
    const float4* __restrict__ src, uint4* __restrict__ dst, int n16)
{
    int i = blockIdx.x * 256 + threadIdx.x;
    if (i >= n16) return;
    uint4 o0, o1;
    perm16(src[4*i], src[4*i+1], src[4*i+2], src[4*i+3], o0, o1);
    dst[2*i] = o0; dst[2*i+1] = o1;
}

// interleave rows: Wc[2h] = perm(Wz[h]), Wc[2h+1] = perm(Wh[h])
__global__ __launch_bounds__(256) void interleave_kernel(
    const float4* __restrict__ Wz, const float4* __restrict__ Wh, uint4* __restrict__ Wc)
{
    int i = blockIdx.x * 256 + threadIdx.x;      // over H_*D_/16 = 65536 groups
    int h = i >> 6;                              // D_/16 = 64 groups per row
    int s = i & 63;
    uint4 z0, z1, h0, h1;
    perm16(Wz[4*i], Wz[4*i+1], Wz[4*i+2], Wz[4*i+3], z0, z1);
    perm16(Wh[4*i], Wh[4*i+1], Wh[4*i+2], Wh[4*i+3], h0, h1);
    uint4* rz = Wc + (size_t)(2*h)   * 128 + 2*s;   // 128 uint4 per row
    uint4* rh = Wc + (size_t)(2*h+1) * 128 + 2*s;
    rz[0] = z0; rz[1] = z1;
    rh[0] = h0; rh[1] = h1;
}

// ============================================================================
// fp16 mma.sync GEMM, tile 128x256, warptile 64x64, BK=64, 3-stage cp.async,
// LDS.64 fragment loads, fused gate epilogue
// ============================================================================
#define BM 128
#define BN 256
#define BK 64
#define ST 80                            // halfs per smem row (pad 16)
#define B_OFF (BM * ST)                  // B rows start (halfs)
#define STG_HALFS ((BM + BN) * ST)       // 30720
#define STG_BYTES (STG_HALFS * 2)        // 61440
#define GEMM_SMEM (3 * STG_BYTES)        // 184320

__device__ __forceinline__ void load_stage(
    uint32_t sb, const __half* __restrict__ Ag, const __half* __restrict__ Bg,
    int k0, int tid)
{
    #pragma unroll
    for (int i = 0; i < 4; i++) {        // A: 128 rows x 8 x 16B
        int s = tid + i * 256;
        int r = s >> 3, c = (s & 7) << 3;
        cpasync16(sb + (uint32_t)(r * ST + c) * 2, Ag + (size_t)r * D_ + k0 + c);
    }
    #pragma unroll
    for (int i = 0; i < 8; i++) {        // B: 256 rows x 8 x 16B
        int s = tid + i * 256;
        int r = s >> 3, c = (s & 7) << 3;
        cpasync16(sb + (uint32_t)(B_OFF + r * ST + c) * 2, Bg + (size_t)r * D_ + k0 + c);
    }
    CP_COMMIT();
}

__global__ __launch_bounds__(256, 1) void gemm_fp16_kernel(
    const __half* __restrict__ X, const __half* __restrict__ Wc,
    const float* __restrict__ bz, const float* __restrict__ bh,
    float* __restrict__ gA, float* __restrict__ gB)
{
    extern __shared__ __align__(16) __half sm[];
    const uint32_t sb = smem_u32(sm);
    const int tid = threadIdx.x;
    const int lane = tid & 31, wid = tid >> 5;
    const int g = lane >> 2, tg = lane & 3;
    const int wm = (wid >> 2) * 64;      // 0 / 64
    const int wn = (wid & 3) * 64;       // 0 / 64 / 128 / 192
    const int bm = blockIdx.y * BM;
    const int bn = blockIdx.x * BN;

    const __half* Ag = X  + (size_t)bm * D_;
    const __half* Bg = Wc + (size_t)bn * D_;

    float c[4][8][4];
    #pragma unroll
    for (int mt = 0; mt < 4; mt++)
        #pragma unroll
        for (int nt = 0; nt < 8; nt++)
            #pragma unroll
            for (int r = 0; r < 4; r++) c[mt][nt][r] = 0.f;

    load_stage(sb,             Ag, Bg, 0,  tid);
    load_stage(sb + STG_BYTES, Ag, Bg, BK, tid);

    const int NK = D_ / BK;   // 16
    for (int kt = 0; kt < NK; kt++) {
        asm volatile("cp.async.wait_group 1;" ::: "memory");
        __syncthreads();
        if (kt + 2 < NK)
            load_stage(sb + (uint32_t)((kt + 2) % 3) * STG_BYTES, Ag, Bg, (kt + 2) * BK, tid);
        else
            CP_COMMIT();

        const __half* As = sm + (kt % 3) * STG_HALFS;
        const __half* Bs = As + B_OFF;

        #pragma unroll
        for (int ks = 0; ks < 4; ks++) {              // 4 k16-groups per BK=64
            const int kb = ks * 16 + 4 * tg;          // fragment offset (halfs)
            uint2 alo[4], ahi[4], bf[8];
            #pragma unroll
            for (int mt = 0; mt < 4; mt++) {
                const int m = wm + mt * 16 + g;
                alo[mt] = *(const uint2*)&As[m * ST + kb];        // {a0, a2}
                ahi[mt] = *(const uint2*)&As[(m + 8) * ST + kb];  // {a1, a3}
            }
            #pragma unroll
            for (int nt = 0; nt < 8; nt++) {
                const int n = wn + nt * 8 + g;
                bf[nt] = *(const uint2*)&Bs[n * ST + kb];         // {b0, b1}
            }
            #pragma unroll
            for (int mt = 0; mt < 4; mt++)
                #pragma unroll
                for (int nt = 0; nt < 8; nt++)
                    mma_fp16(c[mt][nt], alo[mt].x, ahi[mt].x, alo[mt].y, ahi[mt].y,
                             bf[nt].x, bf[nt].y);
        }
    }

    // epilogue: C columns are interleaved (k, ph) pairs -> gates -> gA/gB
    const int hbase = (bn >> 1) + (wn >> 1);   // 128 h per block, 32 per warp
    #pragma unroll
    for (int nt = 0; nt < 8; nt++) {
        const int h = hbase + nt * 4 + tg;
        const float bzv = bz[h], bhv = bh[h];
        #pragma unroll
        for (int mt = 0; mt < 4; mt++) {
            const int m = bm + wm + mt * 16 + g;
            float a0, b0, a1, b1;
            gates2(c[mt][nt][0] + bzv, c[mt][nt][1] + bhv, a0, b0);
            gates2(c[mt][nt][2] + bzv, c[mt][nt][3] + bhv, a1, b1);
            gA[(size_t)m * H_ + h]       = a0;
            gB[(size_t)m * H_ + h]       = b0;
            gA[(size_t)(m + 8) * H_ + h] = a1;
            gB[(size_t)(m + 8) * H_ + h] = b1;
        }
    }
}

// ============================================================================
// chunked scan (gates precomputed in GEMM epilogue)
// ============================================================================
__global__ __launch_bounds__(128) void scanA_kernel(
    const float* __restrict__ gA, const float* __restrict__ gB,
    float* __restrict__ As, float* __restrict__ Bs)
{
    const int h = blockIdx.x * 128 + threadIdx.x;
    const int c = blockIdx.y, b = blockIdx.z;
    const size_t m0 = (size_t)b * S_ + (size_t)c * CL_;
    const float* pa = gA + m0 * H_ + h;
    const float* pb = gB + m0 * H_ + h;
    float A = 1.f, Bv = 0.f;
    for (int t = 0; t < CL_; t += 4) {
        float a0 = pa[0],     b0 = pb[0];
        float a1 = pa[H_],    b1 = pb[H_];
        float a2 = pa[2*H_],  b2 = pb[2*H_];
        float a3 = pa[3*H_],  b3 = pb[3*H_];
        pa += 4 * H_; pb += 4 * H_;
        Bv = fmaf(a0, Bv, b0); A *= a0;
        Bv = fmaf(a1, Bv, b1); A *= a1;
        Bv = fmaf(a2, Bv, b2); A *= a2;
        Bv = fmaf(a3, Bv, b3); A *= a3;
    }
    const size_t o = ((size_t)b * NC_ + c) * H_ + h;
    As[o] = A; Bs[o] = Bv;
}

__global__ __launch_bounds__(128) void scanB_kernel(
    const float* __restrict__ As, const float* __restrict__ Bs, float* __restrict__ Hs)
{
    const int h = blockIdx.x * 128 + threadIdx.x;
    const int b = blockIdx.y;
    float hv = 0.5f;
    for (int c = 0; c < NC_; c++) {
        const size_t o = ((size_t)b * NC_ + c) * H_ + h;
        Hs[o] = hv;
        hv = fmaf(As[o], hv, Bs[o]);
    }
}

template<int MODE>   // 0: write fp16 K-permuted (next-layer GEMM input); 1: fp32 out
__global__ __launch_bounds__(128) void scanC_kernel(
    const float* __restrict__ gA, const float* __restrict__ gB,
    const float* __restrict__ Hs, float* __restrict__ outF, __half* __restrict__ outH)
{
    const int h = blockIdx.x * 128 + threadIdx.x;
    const int c = blockIdx.y, b = blockIdx.z;
    const size_t m0 = (size_t)b * S_ + (size_t)c * CL_;
    const float* pa = gA + m0 * H_ + h;
    const float* pb = gB + m0 * H_ + h;
    float hv = Hs[((size_t)b * NC_ + c) * H_ + h];
    const int hp = (MODE == 0) ? permcol16(h) : h;
    float*  pf = (MODE == 1) ? outF + m0 * H_ + hp : nullptr;
    __half* ph = (MODE == 0) ? outH + m0 * H_ + hp : nullptr;
    for (int t = 0; t < CL_; t += 4) {
        float a0 = pa[0],     b0 = pb[0];
        float a1 = pa[H_],    b1 = pb[H_];
        float a2 = pa[2*H_],  b2 = pb[2*H_];
        float a3 = pa[3*H_],  b3 = pb[3*H_];
        pa += 4 * H_; pb += 4 * H_;
        hv = fmaf(a0, hv, b0);
        if (MODE == 0) ph[0]    = __float2half_rn(hv); else pf[0]    = hv;
        hv = fmaf(a1, hv, b1);
        if (MODE == 0) ph[H_]   = __float2half_rn(hv); else pf[H_]   = hv;
        hv = fmaf(a2, hv, b2);
        if (MODE == 0) ph[2*H_] = __float2half_rn(hv); else pf[2*H_] = hv;
        hv = fmaf(a3, hv, b3);
        if (MODE == 0) ph[3*H_] = __float2half_rn(hv); else pf[3*H_] = hv;
        if (MODE == 0) ph += 4 * H_; else pf += 4 * H_;
    }
}

// ============================================================================
// launch
// ============================================================================
extern "C" void kernel_launch(void* const* d_in, const int* in_sizes, int n_in,
                              void* d_out, int out_size)
{
    const float* x  = (const float*)d_in[0];
    const float* Wz = (const float*)d_in[1];
    const float* bz = (const float*)d_in[2];
    const float* Wh = (const float*)d_in[3];
    const float* bh = (const float*)d_in[4];
    float* out = (float*)d_out;

    __half *Xh, *Wc;
    float *gA, *gB, *As, *Bs, *Hs;
    cudaGetSymbolAddress((void**)&Xh, g_Xh);
    cudaGetSymbolAddress((void**)&Wc, g_Wc);
    cudaGetSymbolAddress((void**)&gA, g_gA);
    cudaGetSymbolAddress((void**)&gB, g_gB);
    cudaGetSymbolAddress((void**)&As, g_As);
    cudaGetSymbolAddress((void**)&Bs, g_Bs);
    cudaGetSymbolAddress((void**)&Hs, g_Hs);

    cudaFuncSetAttribute(gemm_fp16_kernel,
                         cudaFuncAttributeMaxDynamicSharedMemorySize, GEMM_SMEM);

    const size_t HD = (size_t)H_ * D_;
    dim3 gemm_grid(N2_ / BN, M_ / BM);     // (8, 128)
    dim3 scanAC_grid(H_ / 128, NC_, B_);   // (8, 16, 8)
    dim3 scanB_grid(H_ / 128, B_);         // (8, 8)

    round_kernel<<<(M_ * (size_t)D_ / 16 + 255) / 256, 256>>>(
        (const float4*)x, (uint4*)Xh, (int)((size_t)M_ * D_ / 16));

    for (int l = 0; l < 2; l++) {
        interleave_kernel<<<(HD / 16 + 255) / 256, 256>>>(
            (const float4*)(Wz + l * HD), (const float4*)(Wh + l * HD), (uint4*)Wc);
        gemm_fp16_kernel<<<gemm_grid, 256, GEMM_SMEM>>>(Xh, Wc,
                                                        bz + l * H_, bh + l * H_, gA, gB);
        scanA_kernel<<<scanAC_grid, 128>>>(gA, gB, As, Bs);
        scanB_kernel<<<scanB_grid, 128>>>(As, Bs, Hs);
        if (l == 0)
            scanC_kernel<0><<<scanAC_grid, 128>>>(gA, gB, Hs, nullptr, Xh);
        else
            scanC_kernel<1><<<scanAC_grid, 128>>>(gA, gB, Hs, out, nullptr);
    }
}